// round 2
// baseline (speedup 1.0000x reference)
#include <cuda_runtime.h>
#include <math.h>

// ---------------- problem constants ----------------
#define HEADS  8
#define HD     128          // head dim = 3072 / (3*8)
#define NSEQ   1024
#define DIM    512
#define INNER  3072
#define BATCH  8            // bt*b_sz = 2*4
#define BH     (BATCH*HEADS)    // 64
#define NTOK   (BATCH*NSEQ)     // 8192
#define SCALE  0.125f       // (dim // HEADS)^-0.5 = 64^-0.5

// ---------------- scratch (device globals; no runtime alloc allowed) ----------------
__device__ float g_Q [BH * NSEQ * HD];   // [bh][n][hd]
__device__ float g_Kt[BH * HD * NSEQ];   // [bh][hd][n]   (transposed for attention)
__device__ float g_V [BH * NSEQ * HD];   // [bh][n][hd]
__device__ float g_O [NTOK * HEADS * HD];// [token][h*128+dd]  (ready for out GEMM)

// =====================================================================
// SGEMM: C(MxN) = A(MxK) @ B(KxN) (+bias), 128x128x8 tile, 8x8/thread
// EPI==0: A=x, scatter into g_Q / g_Kt / g_V with b_qkv
// EPI==1: A=g_O (device symbol), write C=d_out with b_out
// =====================================================================
template<int EPI>
__global__ void __launch_bounds__(256)
sgemm_kernel(const float* __restrict__ A, const float* __restrict__ B,
             const float* __restrict__ bias, float* __restrict__ C,
             int M, int N, int K)
{
    constexpr int BM = 128, BN = 128, BK = 8, TM = 8, TN = 8;
    __shared__ float As[BK][BM];
    __shared__ float Bs[BK][BN];

    const int tid     = threadIdx.x;
    const int rowBase = blockIdx.y * BM;
    const int colBase = blockIdx.x * BN;

    const float* Asrc = (EPI == 1) ? g_O : A;

    const int aRow = tid >> 1;            // 0..127
    const int aCol = (tid & 1) << 2;      // 0 or 4
    const int bRow = tid >> 5;            // 0..7
    const int bCol = (tid & 31) << 2;     // 0..124
    const int tr   = tid >> 4;            // 0..15
    const int tc   = tid & 15;            // 0..15

    float acc[TM][TN] = {};

    const float* Ab = Asrc + (size_t)rowBase * K;
    const float* Bb = B    + colBase;

    for (int k0 = 0; k0 < K; k0 += BK) {
        float4 av = *(const float4*)(Ab + (size_t)aRow * K + k0 + aCol);
        As[aCol + 0][aRow] = av.x;
        As[aCol + 1][aRow] = av.y;
        As[aCol + 2][aRow] = av.z;
        As[aCol + 3][aRow] = av.w;
        *(float4*)&Bs[bRow][bCol] = *(const float4*)(Bb + (size_t)(k0 + bRow) * N + bCol);
        __syncthreads();

        #pragma unroll
        for (int kk = 0; kk < BK; kk++) {
            float ra[TM], rb[TN];
            *(float4*)&ra[0] = *(const float4*)&As[kk][tr * TM];
            *(float4*)&ra[4] = *(const float4*)&As[kk][tr * TM + 4];
            *(float4*)&rb[0] = *(const float4*)&Bs[kk][tc * TN];
            *(float4*)&rb[4] = *(const float4*)&Bs[kk][tc * TN + 4];
            #pragma unroll
            for (int i = 0; i < TM; i++)
                #pragma unroll
                for (int j = 0; j < TN; j++)
                    acc[i][j] += ra[i] * rb[j];
        }
        __syncthreads();
    }

    if (EPI == 0) {
        // scatter qkv: col nn -> (part, head, dd); row m -> (bidx, ni)
        #pragma unroll
        for (int i = 0; i < TM; i++) {
            const int m    = rowBase + tr * TM + i;
            const int bidx = m >> 10;
            const int ni   = m & 1023;
            #pragma unroll
            for (int j = 0; j < TN; j++) {
                const int nn   = colBase + tc * TN + j;
                const float v  = acc[i][j] + bias[nn];
                const int part = nn >> 10;
                const int h    = (nn >> 7) & 7;
                const int dd   = nn & 127;
                const int bh   = bidx * HEADS + h;
                if (part == 0)
                    g_Q[((size_t)bh * NSEQ + ni) * HD + dd] = v;
                else if (part == 1)
                    g_Kt[((size_t)bh * HD + dd) * NSEQ + ni] = v;
                else
                    g_V[((size_t)bh * NSEQ + ni) * HD + dd] = v;
            }
        }
    } else {
        #pragma unroll
        for (int i = 0; i < TM; i++) {
            const int m = rowBase + tr * TM + i;
            #pragma unroll
            for (int j = 0; j < TN; j += 4) {
                const int nn = colBase + tc * TN + j;
                float4 v;
                v.x = acc[i][j + 0] + bias[nn + 0];
                v.y = acc[i][j + 1] + bias[nn + 1];
                v.z = acc[i][j + 2] + bias[nn + 2];
                v.w = acc[i][j + 3] + bias[nn + 3];
                *(float4*)(C + (size_t)m * N + nn) = v;
            }
        }
    }
}

// =====================================================================
// Flash attention (fp32, online softmax).
// grid = (16 q-tiles, 64 bh), block = 256 (16x16).
// Per CTA: 64 q rows, loop over 16 kv tiles of 64.
// Thread tile: S 4x4 (rows 4*ty.., kv cols 4*tx..), O 4x8 (d cols 8*tx..).
// =====================================================================
#define SQ_PITCH 132   // 128 + 4 : conflict-free broadcast reads
#define SK_PITCH 68    // 64 + 4  : conflict-free lane-consecutive float4
#define SV_PITCH 128
#define SP_PITCH 68

#define ATT_SMEM_FLOATS (64*SQ_PITCH + 128*SK_PITCH + 64*SV_PITCH + 64*SP_PITCH)
#define ATT_SMEM_BYTES  (ATT_SMEM_FLOATS * 4)

__global__ void __launch_bounds__(256)
attn_kernel()
{
    extern __shared__ float sm[];
    float* sQ  = sm;                        // [64][SQ_PITCH]
    float* sKt = sQ  + 64 * SQ_PITCH;       // [128][SK_PITCH]
    float* sV  = sKt + 128 * SK_PITCH;      // [64][SV_PITCH]
    float* sP  = sV  + 64 * SV_PITCH;       // [64][SP_PITCH]

    const int bh = blockIdx.y;
    const int q0 = blockIdx.x * 64;
    const int tid = threadIdx.x;
    const int ty = tid >> 4;
    const int tx = tid & 15;

    // ---- load Q tile (64 x 128) ----
    const float* Qg = g_Q + ((size_t)bh * NSEQ + q0) * HD;
    {
        const int c4 = (tid & 31) << 2;
        for (int r = tid >> 5; r < 64; r += 8)
            *(float4*)&sQ[r * SQ_PITCH + c4] = *(const float4*)(Qg + r * HD + c4);
    }

    float o[4][8] = {};
    float rm[4] = { -1e30f, -1e30f, -1e30f, -1e30f };
    float rl[4] = { 0.f, 0.f, 0.f, 0.f };

    const float* Kbase = g_Kt + (size_t)bh * HD * NSEQ;
    const float* Vbase = g_V  + (size_t)bh * NSEQ * HD;

    for (int t = 0; t < 16; t++) {
        const int n0 = t * 64;
        __syncthreads();   // prev PV done before overwriting sKt/sV

        // load K^T tile: sKt[dd][c] <- g_Kt[bh][dd][n0+c]
        {
            const int c4 = (tid & 15) << 2;
            for (int dd = tid >> 4; dd < 128; dd += 16)
                *(float4*)&sKt[dd * SK_PITCH + c4] =
                    *(const float4*)(Kbase + (size_t)dd * NSEQ + n0 + c4);
        }
        // load V tile: sV[r][dd]
        {
            const int c4 = (tid & 31) << 2;
            for (int r = tid >> 5; r < 64; r += 8)
                *(float4*)&sV[r * SV_PITCH + c4] =
                    *(const float4*)(Vbase + (size_t)(n0 + r) * HD + c4);
        }
        __syncthreads();

        // ---- S = Q @ K^T (4x4 per thread) ----
        float s[4][4] = {};
        #pragma unroll 4
        for (int d4 = 0; d4 < HD; d4 += 4) {
            float4 q4[4];
            #pragma unroll
            for (int i = 0; i < 4; i++)
                q4[i] = *(const float4*)&sQ[(4 * ty + i) * SQ_PITCH + d4];
            #pragma unroll
            for (int u = 0; u < 4; u++) {
                const float4 kk = *(const float4*)&sKt[(d4 + u) * SK_PITCH + 4 * tx];
                #pragma unroll
                for (int i = 0; i < 4; i++) {
                    const float qv = ((const float*)&q4[i])[u];
                    s[i][0] += qv * kk.x;
                    s[i][1] += qv * kk.y;
                    s[i][2] += qv * kk.z;
                    s[i][3] += qv * kk.w;
                }
            }
        }

        // ---- online softmax update (rows owned by ty, reduce over tx/16) ----
        #pragma unroll
        for (int i = 0; i < 4; i++) {
            float p0 = s[i][0] * SCALE;
            float p1 = s[i][1] * SCALE;
            float p2 = s[i][2] * SCALE;
            float p3 = s[i][3] * SCALE;
            float mx = fmaxf(fmaxf(p0, p1), fmaxf(p2, p3));
            #pragma unroll
            for (int off = 8; off; off >>= 1)
                mx = fmaxf(mx, __shfl_xor_sync(0xffffffffu, mx, off, 16));
            const float m_new = fmaxf(rm[i], mx);
            const float alpha = __expf(rm[i] - m_new);
            rm[i] = m_new;
            p0 = __expf(p0 - m_new);
            p1 = __expf(p1 - m_new);
            p2 = __expf(p2 - m_new);
            p3 = __expf(p3 - m_new);
            float ls = p0 + p1 + p2 + p3;
            #pragma unroll
            for (int off = 8; off; off >>= 1)
                ls += __shfl_xor_sync(0xffffffffu, ls, off, 16);
            rl[i] = rl[i] * alpha + ls;
            #pragma unroll
            for (int j = 0; j < 8; j++) o[i][j] *= alpha;
            float4 pv = { p0, p1, p2, p3 };
            *(float4*)&sP[(4 * ty + i) * SP_PITCH + 4 * tx] = pv;
        }
        __syncthreads();

        // ---- O += P @ V (4x8 per thread) ----
        #pragma unroll 4
        for (int kv4 = 0; kv4 < 64; kv4 += 4) {
            float4 pp[4];
            #pragma unroll
            for (int i = 0; i < 4; i++)
                pp[i] = *(const float4*)&sP[(4 * ty + i) * SP_PITCH + kv4];
            #pragma unroll
            for (int u = 0; u < 4; u++) {
                const float4 va = *(const float4*)&sV[(kv4 + u) * SV_PITCH + 8 * tx];
                const float4 vb = *(const float4*)&sV[(kv4 + u) * SV_PITCH + 8 * tx + 4];
                #pragma unroll
                for (int i = 0; i < 4; i++) {
                    const float pvv = ((const float*)&pp[i])[u];
                    o[i][0] += pvv * va.x;
                    o[i][1] += pvv * va.y;
                    o[i][2] += pvv * va.z;
                    o[i][3] += pvv * va.w;
                    o[i][4] += pvv * vb.x;
                    o[i][5] += pvv * vb.y;
                    o[i][6] += pvv * vb.z;
                    o[i][7] += pvv * vb.w;
                }
            }
        }
    }

    // ---- finalize + store to g_O (token-major) ----
    const int bidx = bh >> 3;
    const int h    = bh & 7;
    #pragma unroll
    for (int i = 0; i < 4; i++) {
        const float inv = 1.0f / rl[i];
        const int ni = q0 + 4 * ty + i;
        float* dst = g_O + ((size_t)(bidx * NSEQ + ni)) * (HEADS * HD) + h * HD + 8 * tx;
        float4 oa = { o[i][0] * inv, o[i][1] * inv, o[i][2] * inv, o[i][3] * inv };
        float4 ob = { o[i][4] * inv, o[i][5] * inv, o[i][6] * inv, o[i][7] * inv };
        *(float4*)(dst)     = oa;
        *(float4*)(dst + 4) = ob;
    }
}

// =====================================================================
// launch
// =====================================================================
extern "C" void kernel_launch(void* const* d_in, const int* in_sizes, int n_in,
                              void* d_out, int out_size)
{
    // map inputs by unique element counts (robust to ordering)
    const float *x = nullptr, *Wqkv = nullptr, *bqkv = nullptr,
                *Wout = nullptr, *bout = nullptr;
    for (int i = 0; i < n_in; i++) {
        switch (in_sizes[i]) {
            case NTOK * DIM:    x    = (const float*)d_in[i]; break;  // 4194304
            case DIM * INNER:   Wqkv = (const float*)d_in[i]; break;  // 1572864
            case INNER:         bqkv = (const float*)d_in[i]; break;  // 3072
            case 1024 * DIM:    Wout = (const float*)d_in[i]; break;  // 524288
            case DIM:           bout = (const float*)d_in[i]; break;  // 512
        }
    }
    float* out = (float*)d_out;

    // opt-in to >48KB dynamic smem for the attention kernel (non-stream API,
    // deterministic, capture-safe)
    (void)cudaFuncSetAttribute(attn_kernel,
                               cudaFuncAttributeMaxDynamicSharedMemorySize,
                               ATT_SMEM_BYTES);

    // 1) QKV projection + scatter (M=8192, N=3072, K=512)
    sgemm_kernel<0><<<dim3(INNER / 128, NTOK / 128), 256>>>(
        x, Wqkv, bqkv, nullptr, NTOK, INNER, DIM);

    // 2) attention
    attn_kernel<<<dim3(NSEQ / 64, BH), 256, ATT_SMEM_BYTES>>>();

    // 3) output projection (M=8192, N=512, K=1024), A = g_O (device symbol)
    sgemm_kernel<1><<<dim3(DIM / 128, NTOK / 128), 256>>>(
        nullptr, Wout, bout, out, NTOK, DIM, HEADS * HD);
}

// round 3
// speedup vs baseline: 3.0691x; 3.0691x over previous
#include <cuda_runtime.h>
#include <math.h>

// ---------------- problem constants ----------------
#define HEADS  8
#define HD     128          // head dim = 3072 / (3*8)
#define NSEQ   1024
#define DIM    512
#define INNER  3072
#define BATCH  8            // bt*b_sz = 2*4
#define BH     (BATCH*HEADS)    // 64
#define NTOK   (BATCH*NSEQ)     // 8192
#define SCALE  0.125f       // (dim // HEADS)^-0.5 = 64^-0.5

// ---------------- scratch (device globals) ----------------
__device__ float g_Q[BH * NSEQ * HD];    // [bh][n][d]
__device__ float g_K[BH * NSEQ * HD];    // [bh][n][d]
__device__ float g_V[BH * NSEQ * HD];    // [bh][n][d]
__device__ float g_O[NTOK * HEADS * HD]; // [token][h*128+dd]

// ---------------- tf32 helpers ----------------
__device__ __forceinline__ unsigned f2tf(float x) {
    unsigned r;
    asm("cvt.rna.tf32.f32 %0, %1;" : "=r"(r) : "f"(x));
    return r;
}

__device__ __forceinline__ void mma8(float* c, const unsigned* a, unsigned b0, unsigned b1) {
    asm volatile(
        "mma.sync.aligned.m16n8k8.row.col.f32.tf32.tf32.f32 "
        "{%0,%1,%2,%3}, {%4,%5,%6,%7}, {%8,%9}, {%0,%1,%2,%3};\n"
        : "+f"(c[0]), "+f"(c[1]), "+f"(c[2]), "+f"(c[3])
        : "r"(a[0]), "r"(a[1]), "r"(a[2]), "r"(a[3]), "r"(b0), "r"(b1));
}

// =====================================================================
// tf32 MMA GEMM: C(MxN) = A(MxK) @ B(KxN) + bias
// 128x128x32 CTA tile, 8 warps, warp tile 64x32 (2x4 warp grid).
// EPI==0: A=x, epilogue scatters into g_Q/g_K/g_V  (N=3072)
// EPI==1: A=g_O, epilogue writes C=d_out           (N=512)
// =====================================================================
#define AP 36     // As pitch (floats): frag addr 4g+tg -> conflict-free
#define BP 136    // Bs pitch: frag addr 8tg+g -> conflict-free

template<int EPI>
__global__ void __launch_bounds__(256)
mma_gemm(const float* __restrict__ A, const float* __restrict__ B,
         const float* __restrict__ bias, float* __restrict__ C,
         int M, int N, int K)
{
    __shared__ unsigned As[128 * AP];
    __shared__ unsigned Bs[32 * BP];

    const int tid  = threadIdx.x;
    const int warp = tid >> 5;
    const int lane = tid & 31;
    const int g    = lane >> 2;
    const int tg   = lane & 3;
    const int wr   = warp >> 2;   // 0..1
    const int wc   = warp & 3;    // 0..3

    const int rowBase = blockIdx.y * 128;
    const int colBase = blockIdx.x * 128;

    const float* Asrc = (EPI == 1) ? g_O : A;

    float c[4][4][4] = {};

    for (int k0 = 0; k0 < K; k0 += 32) {
        // stage A tile (128x32) as tf32
        #pragma unroll
        for (int i = 0; i < 4; i++) {
            int f  = tid + i * 256;           // float4 index, 1024 total
            int m  = f >> 3;
            int kc = (f & 7) << 2;
            float4 v = *(const float4*)(Asrc + (size_t)(rowBase + m) * K + k0 + kc);
            As[m * AP + kc + 0] = f2tf(v.x);
            As[m * AP + kc + 1] = f2tf(v.y);
            As[m * AP + kc + 2] = f2tf(v.z);
            As[m * AP + kc + 3] = f2tf(v.w);
        }
        // stage B tile (32x128) as tf32
        #pragma unroll
        for (int i = 0; i < 4; i++) {
            int f  = tid + i * 256;
            int kr = f >> 5;
            int nc = (f & 31) << 2;
            float4 v = *(const float4*)(B + (size_t)(k0 + kr) * N + colBase + nc);
            Bs[kr * BP + nc + 0] = f2tf(v.x);
            Bs[kr * BP + nc + 1] = f2tf(v.y);
            Bs[kr * BP + nc + 2] = f2tf(v.z);
            Bs[kr * BP + nc + 3] = f2tf(v.w);
        }
        __syncthreads();

        #pragma unroll
        for (int ks = 0; ks < 4; ks++) {
            const int kb = ks * 8;
            unsigned a[4][4], b[4][2];
            #pragma unroll
            for (int mt = 0; mt < 4; mt++) {
                const int rb = wr * 64 + mt * 16;
                a[mt][0] = As[(rb + g)     * AP + kb + tg];
                a[mt][1] = As[(rb + g + 8) * AP + kb + tg];
                a[mt][2] = As[(rb + g)     * AP + kb + tg + 4];
                a[mt][3] = As[(rb + g + 8) * AP + kb + tg + 4];
            }
            #pragma unroll
            for (int nt = 0; nt < 4; nt++) {
                const int cb = wc * 32 + nt * 8;
                b[nt][0] = Bs[(kb + tg)     * BP + cb + g];
                b[nt][1] = Bs[(kb + tg + 4) * BP + cb + g];
            }
            #pragma unroll
            for (int mt = 0; mt < 4; mt++)
                #pragma unroll
                for (int nt = 0; nt < 4; nt++)
                    mma8(c[mt][nt], a[mt], b[nt][0], b[nt][1]);
        }
        __syncthreads();
    }

    // ---------------- epilogue ----------------
    #pragma unroll
    for (int mt = 0; mt < 4; mt++) {
        const int r0 = rowBase + wr * 64 + mt * 16 + g;
        const int r1 = r0 + 8;
        #pragma unroll
        for (int nt = 0; nt < 4; nt++) {
            const int col0 = colBase + wc * 32 + nt * 8 + 2 * tg;
            const float b0 = bias[col0], b1 = bias[col0 + 1];
            float2 v0 = { c[mt][nt][0] + b0, c[mt][nt][1] + b1 };  // row r0
            float2 v1 = { c[mt][nt][2] + b0, c[mt][nt][3] + b1 };  // row r1
            if (EPI == 0) {
                const int part = col0 >> 10;
                const int h    = (col0 >> 7) & 7;
                const int dd   = col0 & 127;
                float* dst = (part == 0) ? g_Q : (part == 1) ? g_K : g_V;
                {
                    const int bh = (r0 >> 10) * HEADS + h;
                    const int ni = r0 & 1023;
                    *(float2*)(dst + ((size_t)bh * NSEQ + ni) * HD + dd) = v0;
                }
                {
                    const int bh = (r1 >> 10) * HEADS + h;
                    const int ni = r1 & 1023;
                    *(float2*)(dst + ((size_t)bh * NSEQ + ni) * HD + dd) = v1;
                }
            } else {
                *(float2*)(C + (size_t)r0 * N + col0) = v0;
                *(float2*)(C + (size_t)r1 * N + col0) = v1;
            }
        }
    }
}

// =====================================================================
// tf32 MMA flash attention.
// grid = (8 q-tiles, 64 bh), block = 256 (8 warps).
// CTA: 128 q rows; warp w owns rows [16w,16w+16). kv tiles of 64, 16 iters.
// S: warp computes 16x64 via 8 n-tiles m16n8k8 over d=128 (16 k-steps).
// PV: warp computes 16x128 via 16 n-tiles over kv=64 (8 k-steps).
// =====================================================================
#define QP 132   // sQ pitch: frag addr 4g+tg conflict-free
#define KP 132   // sK pitch: frag addr 4g+tg conflict-free
#define VP 136   // sV pitch: frag addr 8tg+g conflict-free
#define PP 68    // sP pitch: frag addr 4g+tg conflict-free

#define ATT_SMEM_UINTS (128*QP + 64*KP + 64*VP + 128*PP)
#define ATT_SMEM_BYTES (ATT_SMEM_UINTS * 4)

__global__ void __launch_bounds__(256)
attn_mma()
{
    extern __shared__ unsigned sm[];
    unsigned* sQ = sm;                 // [128][QP]
    unsigned* sK = sQ + 128 * QP;      // [64][KP]
    unsigned* sV = sK + 64 * KP;       // [64][VP]
    unsigned* sP = sV + 64 * VP;       // [128][PP]

    const int bh  = blockIdx.y;
    const int q0  = blockIdx.x * 128;
    const int tid = threadIdx.x;
    const int warp = tid >> 5;
    const int lane = tid & 31;
    const int g    = lane >> 2;
    const int tg   = lane & 3;
    const int wrow = warp * 16;

    const float* Qg = g_Q + ((size_t)bh * NSEQ + q0) * HD;
    const float* Kg = g_K + (size_t)bh * NSEQ * HD;
    const float* Vg = g_V + (size_t)bh * NSEQ * HD;

    // load Q tile (128 x 128) -> tf32
    #pragma unroll
    for (int i = 0; i < 16; i++) {
        int f  = tid + i * 256;       // of 4096 float4
        int r  = f >> 5;
        int c4 = (f & 31) << 2;
        float4 v = *(const float4*)(Qg + (size_t)r * HD + c4);
        sQ[r * QP + c4 + 0] = f2tf(v.x);
        sQ[r * QP + c4 + 1] = f2tf(v.y);
        sQ[r * QP + c4 + 2] = f2tf(v.z);
        sQ[r * QP + c4 + 3] = f2tf(v.w);
    }

    float o[16][4] = {};
    float rm0 = -1e30f, rm1 = -1e30f, rl0 = 0.f, rl1 = 0.f;

    for (int t = 0; t < 16; t++) {
        const int n0 = t * 64;
        __syncthreads();   // previous iter done with sK/sV

        #pragma unroll
        for (int i = 0; i < 8; i++) {
            int f  = tid + i * 256;   // of 2048 float4
            int r  = f >> 5;
            int c4 = (f & 31) << 2;
            float4 kv = *(const float4*)(Kg + (size_t)(n0 + r) * HD + c4);
            sK[r * KP + c4 + 0] = f2tf(kv.x);
            sK[r * KP + c4 + 1] = f2tf(kv.y);
            sK[r * KP + c4 + 2] = f2tf(kv.z);
            sK[r * KP + c4 + 3] = f2tf(kv.w);
            float4 vv = *(const float4*)(Vg + (size_t)(n0 + r) * HD + c4);
            sV[r * VP + c4 + 0] = f2tf(vv.x);
            sV[r * VP + c4 + 1] = f2tf(vv.y);
            sV[r * VP + c4 + 2] = f2tf(vv.z);
            sV[r * VP + c4 + 3] = f2tf(vv.w);
        }
        __syncthreads();

        // ---- S = Q @ K^T : cs[8][4] ----
        float cs[8][4] = {};
        #pragma unroll 4
        for (int ks = 0; ks < 16; ks++) {
            const int kb = ks * 8;
            unsigned a[4];
            a[0] = sQ[(wrow + g)     * QP + kb + tg];
            a[1] = sQ[(wrow + g + 8) * QP + kb + tg];
            a[2] = sQ[(wrow + g)     * QP + kb + tg + 4];
            a[3] = sQ[(wrow + g + 8) * QP + kb + tg + 4];
            #pragma unroll
            for (int nt = 0; nt < 8; nt++) {
                unsigned b0 = sK[(nt * 8 + g) * KP + kb + tg];
                unsigned b1 = sK[(nt * 8 + g) * KP + kb + tg + 4];
                mma8(cs[nt], a, b0, b1);
            }
        }

        // ---- online softmax on fragments ----
        #pragma unroll
        for (int nt = 0; nt < 8; nt++) {
            cs[nt][0] *= SCALE; cs[nt][1] *= SCALE;
            cs[nt][2] *= SCALE; cs[nt][3] *= SCALE;
        }
        float mx0 = -1e30f, mx1 = -1e30f;
        #pragma unroll
        for (int nt = 0; nt < 8; nt++) {
            mx0 = fmaxf(mx0, fmaxf(cs[nt][0], cs[nt][1]));
            mx1 = fmaxf(mx1, fmaxf(cs[nt][2], cs[nt][3]));
        }
        mx0 = fmaxf(mx0, __shfl_xor_sync(0xffffffffu, mx0, 1));
        mx0 = fmaxf(mx0, __shfl_xor_sync(0xffffffffu, mx0, 2));
        mx1 = fmaxf(mx1, __shfl_xor_sync(0xffffffffu, mx1, 1));
        mx1 = fmaxf(mx1, __shfl_xor_sync(0xffffffffu, mx1, 2));

        const float mn0 = fmaxf(rm0, mx0);
        const float mn1 = fmaxf(rm1, mx1);
        const float alpha0 = __expf(rm0 - mn0);
        const float alpha1 = __expf(rm1 - mn1);
        rm0 = mn0; rm1 = mn1;

        float ls0 = 0.f, ls1 = 0.f;
        #pragma unroll
        for (int nt = 0; nt < 8; nt++) {
            const float p0 = __expf(cs[nt][0] - mn0);
            const float p1 = __expf(cs[nt][1] - mn0);
            const float p2 = __expf(cs[nt][2] - mn1);
            const float p3 = __expf(cs[nt][3] - mn1);
            ls0 += p0 + p1;
            ls1 += p2 + p3;
            const int col = nt * 8 + 2 * tg;
            sP[(wrow + g)     * PP + col]     = f2tf(p0);
            sP[(wrow + g)     * PP + col + 1] = f2tf(p1);
            sP[(wrow + g + 8) * PP + col]     = f2tf(p2);
            sP[(wrow + g + 8) * PP + col + 1] = f2tf(p3);
        }
        ls0 += __shfl_xor_sync(0xffffffffu, ls0, 1);
        ls0 += __shfl_xor_sync(0xffffffffu, ls0, 2);
        ls1 += __shfl_xor_sync(0xffffffffu, ls1, 1);
        ls1 += __shfl_xor_sync(0xffffffffu, ls1, 2);
        rl0 = rl0 * alpha0 + ls0;
        rl1 = rl1 * alpha1 + ls1;

        #pragma unroll
        for (int nt2 = 0; nt2 < 16; nt2++) {
            o[nt2][0] *= alpha0; o[nt2][1] *= alpha0;
            o[nt2][2] *= alpha1; o[nt2][3] *= alpha1;
        }
        __syncwarp();   // sP rows written by this warp, read by this warp

        // ---- O += P @ V ----
        #pragma unroll
        for (int ks = 0; ks < 8; ks++) {
            const int kb = ks * 8;
            unsigned a[4];
            a[0] = sP[(wrow + g)     * PP + kb + tg];
            a[1] = sP[(wrow + g + 8) * PP + kb + tg];
            a[2] = sP[(wrow + g)     * PP + kb + tg + 4];
            a[3] = sP[(wrow + g + 8) * PP + kb + tg + 4];
            #pragma unroll
            for (int nt2 = 0; nt2 < 16; nt2++) {
                unsigned b0 = sV[(kb + tg)     * VP + nt2 * 8 + g];
                unsigned b1 = sV[(kb + tg + 4) * VP + nt2 * 8 + g];
                mma8(o[nt2], a, b0, b1);
            }
        }
        __syncwarp();   // done reading sP before next-iter rewrite
    }

    // ---- finalize ----
    const float inv0 = 1.0f / rl0;
    const float inv1 = 1.0f / rl1;
    const int bidx = bh >> 3;
    const int h    = bh & 7;
    const int ni0  = q0 + wrow + g;
    const int ni1  = ni0 + 8;
    float* O0 = g_O + ((size_t)(bidx * NSEQ + ni0)) * (HEADS * HD) + h * HD;
    float* O1 = g_O + ((size_t)(bidx * NSEQ + ni1)) * (HEADS * HD) + h * HD;
    #pragma unroll
    for (int nt2 = 0; nt2 < 16; nt2++) {
        const int col = nt2 * 8 + 2 * tg;
        float2 v0 = { o[nt2][0] * inv0, o[nt2][1] * inv0 };
        float2 v1 = { o[nt2][2] * inv1, o[nt2][3] * inv1 };
        *(float2*)(O0 + col) = v0;
        *(float2*)(O1 + col) = v1;
    }
}

// =====================================================================
// launch
// =====================================================================
extern "C" void kernel_launch(void* const* d_in, const int* in_sizes, int n_in,
                              void* d_out, int out_size)
{
    const float *x = nullptr, *Wqkv = nullptr, *bqkv = nullptr,
                *Wout = nullptr, *bout = nullptr;
    for (int i = 0; i < n_in; i++) {
        switch (in_sizes[i]) {
            case NTOK * DIM:  x    = (const float*)d_in[i]; break;
            case DIM * INNER: Wqkv = (const float*)d_in[i]; break;
            case INNER:       bqkv = (const float*)d_in[i]; break;
            case 1024 * DIM:  Wout = (const float*)d_in[i]; break;
            case DIM:         bout = (const float*)d_in[i]; break;
        }
    }
    float* out = (float*)d_out;

    (void)cudaFuncSetAttribute(attn_mma,
                               cudaFuncAttributeMaxDynamicSharedMemorySize,
                               ATT_SMEM_BYTES);

    // 1) QKV projection + scatter (M=8192, N=3072, K=512)
    mma_gemm<0><<<dim3(INNER / 128, NTOK / 128), 256>>>(
        x, Wqkv, bqkv, nullptr, NTOK, INNER, DIM);

    // 2) attention (tf32 mma flash)
    attn_mma<<<dim3(NSEQ / 128, BH), 256, ATT_SMEM_BYTES>>>();

    // 3) output projection (M=8192, N=512, K=1024)
    mma_gemm<1><<<dim3(DIM / 128, NTOK / 128), 256>>>(
        nullptr, Wout, bout, out, NTOK, DIM, HEADS * HD);
}